// round 13
// baseline (speedup 1.0000x reference)
#include <cuda_runtime.h>
#include <cuda_bf16.h>

#define NB 8
#define NN 2048
#define NTHREADS 256
#define RPB 8                         // rows per block (same batch: 2048 % 8 == 0)
#define NWARPS (NTHREADS / 32)        // 8

struct P3 { float x, y, z; };

// Load 4 consecutive columns' coordinates (12 floats, 16B-aligned), pre-scaled.
__device__ __forceinline__ void load_cols4(const float* __restrict__ cb,
                                           int col0, float sc, P3 p[4])
{
    const float4* f = reinterpret_cast<const float4*>(cb + 3 * col0);
    float4 f0 = f[0], f1 = f[1], f2 = f[2];
    p[0] = { f0.x * sc, f0.y * sc, f0.z * sc };
    p[1] = { f0.w * sc, f1.x * sc, f1.y * sc };
    p[2] = { f1.z * sc, f1.w * sc, f2.x * sc };
    p[3] = { f2.y * sc, f2.z * sc, f2.w * sc };
}

// Masked Gaussian for 4 columns (coords pre-scaled by sqrt(log2e)/sigma):
// a = exp2(-(dx^2+dy^2+dz^2)) * m  ==  exp(-d/sigma^2) * m
__device__ __forceinline__ float4 gauss4(P3 ci, const P3 p[4], float4 m)
{
    float4 a;
    #pragma unroll
    for (int k = 0; k < 4; k++) {
        float dx = ci.x - p[k].x;
        float dy = ci.y - p[k].y;
        float dz = ci.z - p[k].z;
        float e  = __fmaf_rn(dx, -dx, __fmaf_rn(dy, -dy, -dz * dz));
        float v  = exp2f(e);
        (&a.x)[k] = v * (&m.x)[k];
    }
    return a;
}

__global__ __launch_bounds__(NTHREADS, 3) void gauss_adj_kernel(
    const float* __restrict__ coords,    // [B, N, 3]
    const float4* __restrict__ masks,    // [B, N, N] as float4
    const float* __restrict__ sigma,     // [1]
    float4* __restrict__ out)            // [B, N, N] as float4
{
    __shared__ P3    sci[RPB];           // scaled query coords for block's rows
    __shared__ float wsum[RPB][NWARPS];  // per-row cross-warp partials

    const int tid  = threadIdx.x;
    const int lane = tid & 31;
    const int wid  = tid >> 5;

    const int row0 = blockIdx.x * RPB;   // first row of this block
    const int b    = row0 >> 11;         // batch index (row0 / N)
    const float* cb = coords + (size_t)b * NN * 3;

    const float4* mptr = masks + (size_t)row0 * (NN / 4);
    float4*       optr = out   + (size_t)row0 * (NN / 4);

    // sqrt(log2(e)) / sigma — folds 1/sigma^2 and the exp->exp2 constant
    // into the coordinate pre-scale.
    const float s  = sigma[0];
    const float sc = __fsqrt_rn(1.4426950408889634f) / s;

    // Per-thread column coordinates (scaled), resident for the whole block.
    P3 pA[4], pB[4];
    load_cols4(cb, 4 * tid,              sc, pA);
    load_cols4(cb, 4 * (tid + NTHREADS), sc, pB);

    // Stage the RPB query-point coords (scaled).
    if (tid < RPB) {
        int i = (row0 + tid) & (NN - 1);
        sci[tid] = { cb[3*i] * sc, cb[3*i + 1] * sc, cb[3*i + 2] * sc };
    }
    __syncthreads();

    // ---- Phase 1: uninterrupted read stream, per-row partial sums only ----
    float rsum[RPB];
    #pragma unroll
    for (int r = 0; r < RPB; r++) {
        const float4* mrow = mptr + (size_t)r * (NN / 4);
        // Default caching: rows stay resident in L1/L2 for the phase-2 reload.
        float4 mA = mrow[tid];
        float4 mB = mrow[tid + NTHREADS];
        const P3 ci = sci[r];
        float4 aA = gauss4(ci, pA, mA);
        float4 aB = gauss4(ci, pB, mB);
        rsum[r] = (aA.x + aA.y) + (aA.z + aA.w)
                + (aB.x + aB.y) + (aB.z + aB.w);
    }

    // ---- Single reduction: 8 shuffle trees, one barrier ----
    #pragma unroll
    for (int r = 0; r < RPB; r++) {
        #pragma unroll
        for (int off = 16; off > 0; off >>= 1)
            rsum[r] += __shfl_down_sync(0xffffffffu, rsum[r], off);
    }
    if (lane == 0) {
        #pragma unroll
        for (int r = 0; r < RPB; r++) wsum[r][wid] = rsum[r];
    }
    __syncthreads();

    float inv[RPB];
    #pragma unroll
    for (int r = 0; r < RPB; r++) {
        float total = 0.0f;
        #pragma unroll
        for (int k = 0; k < NWARPS; k++) total += wsum[r][k];
        inv[r] = 1.0f / (total + 1e-8f);
    }

    // ---- Phase 2: reload masks (cache hit), recompute, normalize, store ----
    #pragma unroll
    for (int r = 0; r < RPB; r++) {
        const float4* mrow = mptr + (size_t)r * (NN / 4);
        float4 mA = __ldcs(mrow + tid);              // last touch: evict-first
        float4 mB = __ldcs(mrow + tid + NTHREADS);
        const P3 ci = sci[r];
        float4 aA = gauss4(ci, pA, mA);
        float4 aB = gauss4(ci, pB, mB);
        const float iv = inv[r];
        float4* orow = optr + (size_t)r * (NN / 4);
        __stcs(orow + tid,            make_float4(aA.x*iv, aA.y*iv, aA.z*iv, aA.w*iv));
        __stcs(orow + tid + NTHREADS, make_float4(aB.x*iv, aB.y*iv, aB.z*iv, aB.w*iv));
    }
}

extern "C" void kernel_launch(void* const* d_in, const int* in_sizes, int n_in,
                              void* d_out, int out_size)
{
    const float*  coords = (const float*)d_in[0];   // [8,2048,3]
    const float4* masks  = (const float4*)d_in[1];  // [8,2048,2048]
    const float*  sigma  = (const float*)d_in[2];   // [1]
    float4*       out    = (float4*)d_out;          // [8,2048,2048]

    (void)in_sizes; (void)n_in; (void)out_size;

    dim3 grid(NB * NN / RPB);   // 2048 blocks
    dim3 block(NTHREADS);
    gauss_adj_kernel<<<grid, block>>>(coords, masks, sigma, out);
}

// round 14
// speedup vs baseline: 1.0868x; 1.0868x over previous
#include <cuda_runtime.h>
#include <cuda_bf16.h>

#define NB 8
#define NN 2048
#define NTHREADS 256
#define RPB 4                         // rows per block (2048 % 4 == 0)
#define NWARPS (NTHREADS / 32)        // 8

struct P3 { float x, y, z; };

// Load 4 consecutive columns' coordinates (12 floats, 16B-aligned), pre-scaled.
__device__ __forceinline__ void load_cols4(const float* __restrict__ cb,
                                           int col0, float sc, P3 p[4])
{
    const float4* f = reinterpret_cast<const float4*>(cb + 3 * col0);
    float4 f0 = f[0], f1 = f[1], f2 = f[2];
    p[0] = { f0.x * sc, f0.y * sc, f0.z * sc };
    p[1] = { f0.w * sc, f1.x * sc, f1.y * sc };
    p[2] = { f1.z * sc, f1.w * sc, f2.x * sc };
    p[3] = { f2.y * sc, f2.z * sc, f2.w * sc };
}

// Masked Gaussian for 4 columns (coords pre-scaled by sqrt(log2e)/sigma):
// a = exp2(-(dx^2+dy^2+dz^2)) * m  ==  exp(-d/sigma^2) * m
__device__ __forceinline__ float4 gauss4(P3 ci, const P3 p[4], float4 m)
{
    float4 a;
    #pragma unroll
    for (int k = 0; k < 4; k++) {
        float dx = ci.x - p[k].x;
        float dy = ci.y - p[k].y;
        float dz = ci.z - p[k].z;
        float e  = __fmaf_rn(dx, -dx, __fmaf_rn(dy, -dy, -dz * dz));
        float v  = exp2f(e);
        (&a.x)[k] = v * (&m.x)[k];
    }
    return a;
}

__global__ __launch_bounds__(NTHREADS, 3) void gauss_adj_kernel(
    const float* __restrict__ coords,    // [B, N, 3]
    const float4* __restrict__ masks,    // [B, N, N] as float4
    const float* __restrict__ sigma,     // [1]
    float4* __restrict__ out)            // [B, N, N] as float4
{
    __shared__ P3    sci[RPB];           // scaled query coords for block's rows
    __shared__ float wsum[RPB][NWARPS];  // per-row cross-warp partials

    const int tid  = threadIdx.x;
    const int lane = tid & 31;
    const int wid  = tid >> 5;

    const int row0 = blockIdx.x * RPB;   // first row of this block
    const int b    = row0 >> 11;         // batch index (row0 / N)
    const float* cb = coords + (size_t)b * NN * 3;

    const float4* mptr = masks + (size_t)row0 * (NN / 4);
    float4*       optr = out   + (size_t)row0 * (NN / 4);

    // Front-batch ALL mask loads for the CTA's 4 rows (8 LDG.128 in flight).
    float4 mA[RPB], mB[RPB];
    #pragma unroll
    for (int r = 0; r < RPB; r++) {
        const float4* mrow = mptr + (size_t)r * (NN / 4);
        mA[r] = __ldcs(mrow + tid);
        mB[r] = __ldcs(mrow + tid + NTHREADS);
    }

    // sqrt(log2(e)) / sigma — folds 1/sigma^2 and the exp->exp2 constant
    // into the coordinate pre-scale.
    const float s  = sigma[0];
    const float sc = __fsqrt_rn(1.4426950408889634f) / s;

    // Per-thread column coordinates (scaled), resident for the whole block.
    P3 pA[4], pB[4];
    load_cols4(cb, 4 * tid,              sc, pA);
    load_cols4(cb, 4 * (tid + NTHREADS), sc, pB);

    // Stage the RPB query-point coords (scaled).
    if (tid < RPB) {
        int i = (row0 + tid) & (NN - 1);
        sci[tid] = { cb[3*i] * sc, cb[3*i + 1] * sc, cb[3*i + 2] * sc };
    }
    __syncthreads();

    // ---- Phase 1: compute all rows' values, keep them in registers ----
    float4 aA[RPB], aB[RPB];
    float  rsum[RPB];
    #pragma unroll
    for (int r = 0; r < RPB; r++) {
        const P3 ci = sci[r];
        aA[r] = gauss4(ci, pA, mA[r]);    // overwrites mask registers' liveness
        aB[r] = gauss4(ci, pB, mB[r]);
        rsum[r] = (aA[r].x + aA[r].y) + (aA[r].z + aA[r].w)
                + (aB[r].x + aB[r].y) + (aB[r].z + aB[r].w);
    }

    // ---- Single reduction: 4 shuffle trees, ONE barrier per CTA ----
    #pragma unroll
    for (int r = 0; r < RPB; r++) {
        #pragma unroll
        for (int off = 16; off > 0; off >>= 1)
            rsum[r] += __shfl_down_sync(0xffffffffu, rsum[r], off);
    }
    if (lane == 0) {
        #pragma unroll
        for (int r = 0; r < RPB; r++) wsum[r][wid] = rsum[r];
    }
    __syncthreads();

    // ---- Phase 2: normalize from registers, pure write burst ----
    #pragma unroll
    for (int r = 0; r < RPB; r++) {
        float total = 0.0f;
        #pragma unroll
        for (int k = 0; k < NWARPS; k++) total += wsum[r][k];
        const float iv = 1.0f / (total + 1e-8f);

        float4* orow = optr + (size_t)r * (NN / 4);
        __stcs(orow + tid,            make_float4(aA[r].x*iv, aA[r].y*iv,
                                                 aA[r].z*iv, aA[r].w*iv));
        __stcs(orow + tid + NTHREADS, make_float4(aB[r].x*iv, aB[r].y*iv,
                                                 aB[r].z*iv, aB[r].w*iv));
    }
}

extern "C" void kernel_launch(void* const* d_in, const int* in_sizes, int n_in,
                              void* d_out, int out_size)
{
    const float*  coords = (const float*)d_in[0];   // [8,2048,3]
    const float4* masks  = (const float4*)d_in[1];  // [8,2048,2048]
    const float*  sigma  = (const float*)d_in[2];   // [1]
    float4*       out    = (float4*)d_out;          // [8,2048,2048]

    (void)in_sizes; (void)n_in; (void)out_size;

    dim3 grid(NB * NN / RPB);   // 4096 blocks
    dim3 block(NTHREADS);
    gauss_adj_kernel<<<grid, block>>>(coords, masks, sigma, out);
}